// round 1
// baseline (speedup 1.0000x reference)
#include <cuda_runtime.h>
#include <math.h>

#define N0 20000
#define N1 20000
#define N2 10000
#define NA 600000
#define NE 400000
#define HD 128
#define RR 13
#define LL 2

// ---------------- scratch (static device globals; no allocation) ----------------
__device__ float g_x0[N0 * HD];
__device__ float g_x1[N1 * HD];
__device__ float g_x2[N2 * HD];
__device__ float g_a0[N0 * HD];
__device__ float g_a1[N1 * HD];
__device__ float g_a2[N2 * HD];
__device__ float g_xl[N0 * HD];
__device__ float g_xr[N0 * HD];
__device__ float g_e[NE];
__device__ unsigned g_m[N0];
__device__ float g_den[N0];
__device__ float g_cnt[N0];

// ---------------- helpers ----------------
__device__ __forceinline__ unsigned fkey(float f) {
    unsigned u = __float_as_uint(f);
    return (u & 0x80000000u) ? ~u : (u | 0x80000000u);
}
__device__ __forceinline__ float funkey(unsigned u) {
    return (u & 0x80000000u) ? __uint_as_float(u & 0x7FFFFFFFu)
                             : __uint_as_float(~u);
}
__device__ __forceinline__ float wsum(float v) {
#pragma unroll
    for (int o = 16; o; o >>= 1) v += __shfl_xor_sync(0xffffffffu, v, o);
    return v;
}

// ---------------- generic zero ----------------
__global__ void zero_f_kernel(float* p, int n) {
    int i = blockIdx.x * blockDim.x + threadIdx.x;
    int st = gridDim.x * blockDim.x;
    for (; i < n; i += st) p[i] = 0.f;
}
__global__ void zero_md_kernel(unsigned* m, float* den, int n) {
    int i = blockIdx.x * blockDim.x + threadIdx.x;
    if (i < n) { m[i] = 0u; den[i] = 0.f; }
}

// ---------------- SGEMM: C[M,128] = A[M,128] @ B[128,128] (+bias | scatter) ----
// BM rows per block, 256 threads; thread tile (BM/16) x 8.
template <int BM, bool SCATTER>
__global__ __launch_bounds__(256, 2) void gemm128_kernel(
    const float* __restrict__ A, const float* __restrict__ B,
    const float* __restrict__ bias, float* __restrict__ C,
    const int* __restrict__ sidx, int M) {
    constexpr int TM = BM / 16;   // 8 or 4
    constexpr int RB = BM / 64;   // 2 or 1
    __shared__ float sB[16 * 128];
    __shared__ float sA[16][BM + 4];

    int tid = threadIdx.x;
    int tx = tid & 15, ty = tid >> 4;
    int rowBase = blockIdx.x * BM;

    float acc[TM][8];
#pragma unroll
    for (int i = 0; i < TM; ++i)
#pragma unroll
        for (int j = 0; j < 8; ++j) acc[i][j] = 0.f;

    int lrow = tid >> 2;          // 0..63
    int lk4 = (tid & 3) << 2;     // 0,4,8,12

    for (int kc = 0; kc < 128; kc += 16) {
        // B tile: rows kc..kc+15 are contiguous 2048 floats
        *(float4*)&sB[tid * 4] = *(const float4*)&B[kc * 128 + tid * 4];
        *(float4*)&sB[1024 + tid * 4] =
            *(const float4*)&B[kc * 128 + 1024 + tid * 4];
        // A tile transposed into sA[k][m]
#pragma unroll
        for (int p = 0; p < RB; ++p) {
            int row = p * 64 + lrow;
            float4 v = make_float4(0.f, 0.f, 0.f, 0.f);
            if (rowBase + row < M)
                v = *(const float4*)&A[(size_t)(rowBase + row) * 128 + kc + lk4];
            sA[lk4 + 0][row] = v.x;
            sA[lk4 + 1][row] = v.y;
            sA[lk4 + 2][row] = v.z;
            sA[lk4 + 3][row] = v.w;
        }
        __syncthreads();
#pragma unroll
        for (int kk = 0; kk < 16; ++kk) {
            float af[TM], bf[8];
#pragma unroll
            for (int p = 0; p < RB; ++p)
                *(float4*)&af[p * 4] = *(const float4*)&sA[kk][p * 64 + ty * 4];
            *(float4*)&bf[0] = *(const float4*)&sB[kk * 128 + tx * 4];
            *(float4*)&bf[4] = *(const float4*)&sB[kk * 128 + 64 + tx * 4];
#pragma unroll
            for (int i = 0; i < TM; ++i)
#pragma unroll
                for (int j = 0; j < 8; ++j) acc[i][j] += af[i] * bf[j];
        }
        __syncthreads();
    }

    float4 b0 = make_float4(0.f, 0.f, 0.f, 0.f), b1 = b0;
    if (!SCATTER) {
        b0 = *(const float4*)&bias[tx * 4];
        b1 = *(const float4*)&bias[64 + tx * 4];
    }
#pragma unroll
    for (int p = 0; p < RB; ++p)
#pragma unroll
        for (int i = 0; i < 4; ++i) {
            int r = rowBase + p * 64 + ty * 4 + i;
            if (r >= M) continue;
            int ii = p * 4 + i;
            if (SCATTER) {
                int di = sidx[r];
                float* o = C + (size_t)di * 128;
                atomicAdd(&o[tx * 4 + 0], acc[ii][0]);
                atomicAdd(&o[tx * 4 + 1], acc[ii][1]);
                atomicAdd(&o[tx * 4 + 2], acc[ii][2]);
                atomicAdd(&o[tx * 4 + 3], acc[ii][3]);
                atomicAdd(&o[64 + tx * 4 + 0], acc[ii][4]);
                atomicAdd(&o[64 + tx * 4 + 1], acc[ii][5]);
                atomicAdd(&o[64 + tx * 4 + 2], acc[ii][6]);
                atomicAdd(&o[64 + tx * 4 + 3], acc[ii][7]);
            } else {
                float4 o0 = make_float4(acc[ii][0] + b0.x, acc[ii][1] + b0.y,
                                        acc[ii][2] + b0.z, acc[ii][3] + b0.w);
                float4 o1 = make_float4(acc[ii][4] + b1.x, acc[ii][5] + b1.y,
                                        acc[ii][6] + b1.z, acc[ii][7] + b1.w);
                *(float4*)&C[(size_t)r * 128 + tx * 4] = o0;
                *(float4*)&C[(size_t)r * 128 + 64 + tx * 4] = o1;
            }
        }
}

// ---------------- atom -> chemical count ----------------
__global__ void count_kernel(const int* __restrict__ hd, float* __restrict__ cnt,
                             int n) {
    int i = blockIdx.x * blockDim.x + threadIdx.x;
    if (i < n) atomicAdd(&cnt[hd[i]], 1.f);
}

// x0 = sum/max(cnt,1) + x_chem
__global__ void combine_kernel(const float* __restrict__ sum,
                               const float* __restrict__ cnt,
                               const float* __restrict__ xc,
                               float* __restrict__ out, int n) {
    int i = blockIdx.x * blockDim.x + threadIdx.x;
    if (i < n) out[i] = sum[i] / fmaxf(cnt[i >> 7], 1.f) + xc[i];
}

// ---------------- edge kernels (one warp per edge) ----------------
__global__ void edge_logits_kernel(const float* __restrict__ xl,
                                   const float* __restrict__ xr,
                                   const int* __restrict__ src,
                                   const int* __restrict__ dst,
                                   const float* __restrict__ a,
                                   float* __restrict__ e,
                                   unsigned* __restrict__ mkey, int E) {
    int w = (blockIdx.x * blockDim.x + threadIdx.x) >> 5;
    int lane = threadIdx.x & 31;
    if (w >= E) return;
    int s = src[w], d = dst[w];
    float4 l4 = *(const float4*)&xl[(size_t)s * 128 + lane * 4];
    float4 r4 = *(const float4*)&xr[(size_t)d * 128 + lane * 4];
    float4 av = *(const float4*)&a[lane * 4];
    float x0 = l4.x + r4.x; x0 = x0 > 0.f ? x0 : 0.2f * x0;
    float x1 = l4.y + r4.y; x1 = x1 > 0.f ? x1 : 0.2f * x1;
    float x2 = l4.z + r4.z; x2 = x2 > 0.f ? x2 : 0.2f * x2;
    float x3 = l4.w + r4.w; x3 = x3 > 0.f ? x3 : 0.2f * x3;
    float p = x0 * av.x + x1 * av.y + x2 * av.z + x3 * av.w;
    p = wsum(p);
    if (lane == 0) {
        e[w] = p;
        atomicMax(&mkey[d], fkey(p));
    }
}

__global__ void edge_denom_kernel(float* __restrict__ e,
                                  const int* __restrict__ dst,
                                  const unsigned* __restrict__ mkey,
                                  float* __restrict__ den, int E) {
    int i = blockIdx.x * blockDim.x + threadIdx.x;
    if (i >= E) return;
    int d = dst[i];
    float ex = expf(e[i] - funkey(mkey[d]));
    e[i] = ex;
    atomicAdd(&den[d], ex);
}

__global__ void edge_scatter_kernel(const float* __restrict__ ex,
                                    const float* __restrict__ xl,
                                    const int* __restrict__ src,
                                    const int* __restrict__ dst,
                                    const float* __restrict__ den,
                                    float* __restrict__ agg, int E) {
    int w = (blockIdx.x * blockDim.x + threadIdx.x) >> 5;
    int lane = threadIdx.x & 31;
    if (w >= E) return;
    int s = src[w], d = dst[w];
    float alpha = ex[w] / fmaxf(den[d], 1e-16f);
    float4 v = *(const float4*)&xl[(size_t)s * 128 + lane * 4];
    float* o = agg + (size_t)d * 128 + lane * 4;
    atomicAdd(o + 0, alpha * v.x);
    atomicAdd(o + 1, alpha * v.y);
    atomicAdd(o + 2, alpha * v.z);
    atomicAdd(o + 3, alpha * v.w);
}

// agg[row][c] += cb[c] for every row (GATv2 output bias applied to all dst rows)
__global__ void addbias_kernel(float* __restrict__ agg,
                               const float* __restrict__ cb, int n) {
    int i = blockIdx.x * blockDim.x + threadIdx.x;
    if (i < n) agg[i] += cb[i & 127];
}

// ---------------- layernorm + relu (warp per row) ----------------
__global__ void ln_relu_kernel(const float* __restrict__ in,
                               const float* __restrict__ g,
                               const float* __restrict__ b,
                               float* __restrict__ out, int N) {
    int row = (blockIdx.x * blockDim.x + threadIdx.x) >> 5;
    int lane = threadIdx.x & 31;
    if (row >= N) return;
    float4 v = *(const float4*)&in[(size_t)row * 128 + lane * 4];
    float s = v.x + v.y + v.z + v.w;
    s = wsum(s);
    float mu = s * (1.f / 128.f);
    float d0 = v.x - mu, d1 = v.y - mu, d2 = v.z - mu, d3 = v.w - mu;
    float ss = d0 * d0 + d1 * d1 + d2 * d2 + d3 * d3;
    ss = wsum(ss);
    float inv = rsqrtf(ss * (1.f / 128.f) + 1e-5f);
    float4 gv = *(const float4*)&g[lane * 4];
    float4 bv = *(const float4*)&b[lane * 4];
    float4 o;
    o.x = fmaxf(d0 * inv * gv.x + bv.x, 0.f);
    o.y = fmaxf(d1 * inv * gv.y + bv.y, 0.f);
    o.z = fmaxf(d2 * inv * gv.z + bv.z, 0.f);
    o.w = fmaxf(d3 * inv * gv.w + bv.w, 0.f);
    *(float4*)&out[(size_t)row * 128 + lane * 4] = o;
}

// ---------------- prediction head: out[N,2] = x @ Wp + bp ----------------
__global__ void pred_kernel(const float* __restrict__ x,
                            const float* __restrict__ Wp,
                            const float* __restrict__ bp,
                            float* __restrict__ out, int N) {
    int row = (blockIdx.x * blockDim.x + threadIdx.x) >> 5;
    int lane = threadIdx.x & 31;
    if (row >= N) return;
    float4 xv = *(const float4*)&x[(size_t)row * 128 + lane * 4];
    float4 w01 = *(const float4*)&Wp[lane * 8];
    float4 w23 = *(const float4*)&Wp[lane * 8 + 4];
    float a0 = xv.x * w01.x + xv.y * w01.z + xv.z * w23.x + xv.w * w23.z;
    float a1 = xv.x * w01.y + xv.y * w01.w + xv.z * w23.y + xv.w * w23.w;
    a0 = wsum(a0);
    a1 = wsum(a1);
    if (lane == 0) {
        out[row * 2 + 0] = a0 + bp[0];
        out[row * 2 + 1] = a1 + bp[1];
    }
}

// ---------------- host orchestration ----------------
extern "C" void kernel_launch(void* const* d_in, const int* in_sizes, int n_in,
                              void* d_out, int out_size) {
    const float* x_atom = (const float*)d_in[0];
    const float* x_chem = (const float*)d_in[1];
    const float* x_gene = (const float*)d_in[2];
    const float* x_assay = (const float*)d_in[3];
    const float* W_mol = (const float*)d_in[4];
    const float* Wl = (const float*)d_in[5];
    const float* Wr = (const float*)d_in[6];
    const float* bl = (const float*)d_in[7];
    const float* br = (const float*)d_in[8];
    const float* att = (const float*)d_in[9];
    const float* cb = (const float*)d_in[10];
    const float* lng = (const float*)d_in[11];
    const float* lnb = (const float*)d_in[12];
    const float* Wp = (const float*)d_in[13];
    const float* bp = (const float*)d_in[14];
    const int* hyper = (const int*)d_in[15];
    const int* eir = (const int*)d_in[16];
    float* out = (float*)d_out;
    (void)in_sizes; (void)n_in; (void)out_size;

    float *px0, *px1, *px2, *pa0, *pa1, *pa2, *pxl, *pxr, *pe, *pden, *pcnt;
    unsigned* pm;
    cudaGetSymbolAddress((void**)&px0, g_x0);
    cudaGetSymbolAddress((void**)&px1, g_x1);
    cudaGetSymbolAddress((void**)&px2, g_x2);
    cudaGetSymbolAddress((void**)&pa0, g_a0);
    cudaGetSymbolAddress((void**)&pa1, g_a1);
    cudaGetSymbolAddress((void**)&pa2, g_a2);
    cudaGetSymbolAddress((void**)&pxl, g_xl);
    cudaGetSymbolAddress((void**)&pxr, g_xr);
    cudaGetSymbolAddress((void**)&pe, g_e);
    cudaGetSymbolAddress((void**)&pm, g_m);
    cudaGetSymbolAddress((void**)&pden, g_den);
    cudaGetSymbolAddress((void**)&pcnt, g_cnt);

    const int T = 256;
    const int ZB = 1024;  // blocks for grid-stride zero

    // ---- atom encoder + bottom-up mean aggregation into chemical ----
    zero_f_kernel<<<ZB, T>>>(pa0, N0 * HD);
    zero_f_kernel<<<(N0 + T - 1) / T, T>>>(pcnt, N0);
    count_kernel<<<(NA + T - 1) / T, T>>>(hyper, pcnt, NA);
    gemm128_kernel<128, true>
        <<<(NA + 127) / 128, T>>>(x_atom, W_mol, nullptr, pa0, hyper, NA);
    combine_kernel<<<(N0 * HD + T - 1) / T, T>>>(pa0, pcnt, x_chem, px0, N0 * HD);

    static const int RS[RR] = {0, 0, 0, 0, 0, 2, 1, 2, 2, 1, 1, 1, 1};
    static const int RD[RR] = {2, 2, 1, 1, 1, 1, 1, 0, 0, 0, 0, 0, 2};
    const int NT[3] = {N0, N1, N2};

    const float* xsrc[3] = {px0, x_gene, x_assay};
    float* agg[3] = {pa0, pa1, pa2};
    float* xnew[3] = {px0, px1, px2};

    for (int l = 0; l < LL; ++l) {
        zero_f_kernel<<<ZB, T>>>(pa0, N0 * HD);
        zero_f_kernel<<<ZB, T>>>(pa1, N1 * HD);
        zero_f_kernel<<<ZB, T>>>(pa2, N2 * HD);
        for (int r = 0; r < RR; ++r) {
            int s = RS[r], d = RD[r];
            int Ns = NT[s], Nd = NT[d];
            size_t wo = (size_t)(l * RR + r);
            gemm128_kernel<64, false><<<(Ns + 63) / 64, T>>>(
                xsrc[s], Wl + wo * HD * HD, bl + wo * HD, pxl, nullptr, Ns);
            gemm128_kernel<64, false><<<(Nd + 63) / 64, T>>>(
                xsrc[d], Wr + wo * HD * HD, br + wo * HD, pxr, nullptr, Nd);
            zero_md_kernel<<<(Nd + T - 1) / T, T>>>(pm, pden, Nd);
            const int* srcp = eir + (size_t)r * 2 * NE;
            const int* dstp = srcp + NE;
            edge_logits_kernel<<<(NE + 7) / 8, T>>>(pxl, pxr, srcp, dstp,
                                                    att + wo * HD, pe, pm, NE);
            edge_denom_kernel<<<(NE + T - 1) / T, T>>>(pe, dstp, pm, pden, NE);
            edge_scatter_kernel<<<(NE + 7) / 8, T>>>(pe, pxl, srcp, dstp, pden,
                                                     agg[d], NE);
            addbias_kernel<<<(Nd * HD + T - 1) / T, T>>>(agg[d], cb + wo * HD,
                                                         Nd * HD);
        }
        for (int t = 0; t < 3; ++t) {
            ln_relu_kernel<<<(NT[t] * 32 + T - 1) / T, T>>>(
                agg[t], lng + (size_t)(l * 3 + t) * HD,
                lnb + (size_t)(l * 3 + t) * HD, xnew[t], NT[t]);
        }
        xsrc[0] = px0; xsrc[1] = px1; xsrc[2] = px2;
    }

    pred_kernel<<<(N0 * 32 + T - 1) / T, T>>>(px0, Wp, bp, out, N0);
}